// round 12
// baseline (speedup 1.0000x reference)
#include <cuda_runtime.h>
#include <cstdint>
#include <math.h>

#define L_ 128
#define N_ 8
#define S_ 16384
#define C_ 256
#define MARGIN 0.08f
#define CAND_CAP (1 << 20)
#define SCAND_CAP 640

typedef unsigned long long ull;
typedef unsigned int u32;

// ---------------- device scratch (no allocations allowed) -------------------
__device__ float g_qproj[N_ * L_ * C_];          // exact fp32 q_proj [n][l][c]
__device__ u32   g_qB[N_ * L_ * C_ / 2];         // bf16x2 Q, [n][l][c/2]
__device__ u32   g_WpB[C_ * C_ / 2];             // bf16x2 Wp, [j][c/2] linear
__device__ float g_WpT[C_ * C_];                 // fp32 transposed weights [c][j]
__device__ float g_WvT[C_ * C_];
__device__ float g_WoT[C_ * C_];
__device__ ull   g_bestA[N_ * L_];               // approx packed max
__device__ ull   g_bestE[N_ * L_];               // exact packed max
__device__ int   g_ncand;
__device__ uint2 g_cand[CAND_CAP];               // {key = n<<21|l<<14|s, approx_bits}

// ---------------- small helpers --------------------------------------------
__device__ __forceinline__ ull pk2(float a, float b) {
    ull r; asm("mov.b64 %0, {%1, %2};" : "=l"(r) : "f"(a), "f"(b)); return r;
}
__device__ __forceinline__ void up2(ull v, float &a, float &b) {
    asm("mov.b64 {%0, %1}, %2;" : "=f"(a), "=f"(b) : "l"(v));
}
#define FMA2(d, a, b) asm("fma.rn.f32x2 %0, %1, %2, %0;" : "+l"(d) : "l"(a), "l"(b))

__device__ __forceinline__ u32 fkey(float f) {
    u32 u = __float_as_uint(f);
    return (u & 0x80000000u) ? ~u : (u | 0x80000000u);
}
__device__ __forceinline__ float unfkey(u32 k) {
    return (k & 0x80000000u) ? __uint_as_float(k & 0x7FFFFFFFu)
                             : __uint_as_float(~k);
}
__device__ __forceinline__ u32 bfp(float lo, float hi) {   // bf16x2 {hi|lo}
    u32 r; asm("cvt.rn.bf16x2.f32 %0, %1, %2;" : "=r"(r) : "f"(hi), "f"(lo));
    return r;
}
__device__ __forceinline__ u32 smem_u32(const void* p) {
    u32 a;
    asm("{ .reg .u64 t; cvta.to.shared.u64 t, %1; cvt.u32.u64 %0, t; }"
        : "=r"(a) : "l"(p));
    return a;
}

// mma.sync m16n8k16 row.col bf16 -> f32 accum
#define MMA16816(c, a0, a1, a2, a3, b0, b1) \
    asm volatile("mma.sync.aligned.m16n8k16.row.col.f32.bf16.bf16.f32 " \
        "{%0,%1,%2,%3}, {%4,%5,%6,%7}, {%8,%9}, {%0,%1,%2,%3};" \
        : "+f"((c)[0]), "+f"((c)[1]), "+f"((c)[2]), "+f"((c)[3]) \
        : "r"(a0), "r"(a1), "r"(a2), "r"(a3), "r"(b0), "r"(b1))

#define LDSM4(d0, d1, d2, d3, a) \
    asm volatile("ldmatrix.sync.aligned.m8n8.x4.shared.b16 {%0,%1,%2,%3}, [%4];" \
        : "=r"(d0), "=r"(d1), "=r"(d2), "=r"(d3) : "r"(a))

#define CPA16(dst, src) \
    asm volatile("cp.async.cg.shared.global [%0], [%1], 16;" \
        :: "r"(dst), "l"(src))
#define CPA_COMMIT() asm volatile("cp.async.commit_group;")
#define CPA_WAIT1()  asm volatile("cp.async.wait_group 1;")
#define CPA_WAIT0()  asm volatile("cp.async.wait_group 0;")

// ---------------- weight prep: transposes + bf16 Wp + init ------------------
__global__ void __launch_bounds__(256)
convWKernel(const float* __restrict__ Wp, const float* __restrict__ Wv,
            const float* __restrict__ Wo) {
    int j = blockIdx.x;
    int c = threadIdx.x;
    if (j < 4) {
        int i = j * 256 + c;
        ull iv = ((ull)fkey(-1e30f)) << 32;
        g_bestA[i] = iv;
        g_bestE[i] = iv;
        if (i == 0) g_ncand = 0;
    }
    float wp = Wp[j * C_ + c];
    g_WpT[c * C_ + j] = wp;
    g_WvT[c * C_ + j] = Wv[j * C_ + c];
    g_WoT[c * C_ + j] = Wo[j * C_ + c];
    if ((c & 1) == 0) {
        float wp1 = Wp[j * C_ + c + 1];
        g_WpB[j * 128 + (c >> 1)] = bfp(wp, wp1);
    }
}

// ---------------- exact fp32 q_proj (FFMA2), 64 blocks x 16 rows ------------
__global__ void __launch_bounds__(256)
qprojKernel(const float* __restrict__ tgt, const float* __restrict__ qpos,
            const float* __restrict__ Wq, const float* __restrict__ bq) {
    __shared__ float As[16 * 33];
    __shared__ float Bs[32 * 258];
    const int tid = threadIdx.x;
    const int tj = tid & 15;
    const int ts = tid >> 4;
    const int row0 = blockIdx.x * 16;

    ull acc[8];
#pragma unroll
    for (int k = 0; k < 8; k++) {
        int j = 32 * k + tj * 2;
        acc[k] = pk2(bq[j], bq[j + 1]);
    }

    for (int kc = 0; kc < C_; kc += 32) {
        if (tid < 128) {
            int lr = tid >> 3, c4 = (tid & 7) * 4;
            int g = (row0 + lr) * C_ + kc + c4;
            float4 a = *(const float4*)(tgt + g);
            float4 b = *(const float4*)(qpos + g);
            float* d = As + lr * 33 + c4;
            d[0] = a.x + b.x; d[1] = a.y + b.y; d[2] = a.z + b.z; d[3] = a.w + b.w;
        }
        {
            int lr = tid >> 1, lh = tid & 1;
#pragma unroll
            for (int it = 0; it < 2; it++) {
                int j = lr + it * 128;
                const float4* pw = (const float4*)(Wq + j * C_ + kc + lh * 16);
#pragma unroll
                for (int i = 0; i < 4; i++) {
                    float4 w = pw[i];
                    int c = lh * 16 + i * 4;
                    Bs[(c + 0) * 258 + j] = w.x;
                    Bs[(c + 1) * 258 + j] = w.y;
                    Bs[(c + 2) * 258 + j] = w.z;
                    Bs[(c + 3) * 258 + j] = w.w;
                }
            }
        }
        __syncthreads();
#pragma unroll 4
        for (int c = 0; c < 32; c++) {
            float av = As[ts * 33 + c];
            ull a2 = pk2(av, av);
#pragma unroll
            for (int k = 0; k < 8; k++) {
                ull b2 = *(const ull*)(Bs + c * 258 + 32 * k + tj * 2);
                FMA2(acc[k], a2, b2);
            }
        }
        __syncthreads();
    }

    int row = row0 + ts;
    int l = row >> 3, n = row & 7;
    float* of = g_qproj + (n * L_ + l) * C_;
#pragma unroll
    for (int k = 0; k < 8; k++) {
        int j = 32 * k + tj * 2;
        *(ull*)(of + j) = acc[k];
        float f0, f1; up2(acc[k], f0, f1);
        g_qB[n * 16384 + l * 128 + (j >> 1)] = bfp(f0, f1);
    }
}

// ---------------- fused mma.sync kernel: unified 12-chunk ring --------------
// Tile: 64 s-rows per block; grid (256, 8). occ 2 (reg bound).
#define STRW 132
#define SMEM_WORDS 23140
#define SMEM_BYTES (SMEM_WORDS * 4)     // 92560

__global__ void __launch_bounds__(256, 2)
fusedMMA(const float* __restrict__ memory, const float* __restrict__ pos,
         const float* __restrict__ bp) {
    extern __shared__ u32 sh[];
    u32* Kb = sh;                              // words 0..8447
    float* sNorm = (float*)(sh + 21120);
    float* sRsq  = (float*)(sh + 21248);
    float* sBias = (float*)(sh + 21312);
    ull*   sBest = (ull*)(sh + 21568);
    int*   sCnt  = (int*)(sh + 21824);
    int*   sBase = (int*)(sh + 21825);
    uint2* sCand = (uint2*)(sh + 21826);       // 640 x uint2 -> ends 23106
    float* sThr  = (float*)(sh + 23106);       // 32 floats

    const int tid = threadIdx.x, lane = tid & 31, w = tid >> 5;
    const int gid = lane >> 2, tig = lane & 3;
    const int wm = w >> 1, wj = w & 1;         // role split (rows x half)
    const int n = blockIdx.y;
    const int srow0 = blockIdx.x * 64;

    const u32 shB = smem_u32(sh);
    const u32 KbB = shB;
    const u32 RingB = shB + 33792;             // 3 x 16896-byte buffers

    // ---- prologue: stage A = bf16(memory+pos) into ring bufs 0-1 ----------
#pragma unroll
    for (int it = 0; it < 8; it++) {
        int idx = tid + it * 256;
        int srow = idx >> 5, cg = (idx & 31) * 8;
        int ga = ((srow0 + srow) * N_ + n) * C_ + cg;
        float4 m0 = *(const float4*)(memory + ga);
        float4 m1 = *(const float4*)(memory + ga + 4);
        float4 p0 = *(const float4*)(pos + ga);
        float4 p1 = *(const float4*)(pos + ga + 4);
        uint4 x;
        x.x = bfp(m0.x + p0.x, m0.y + p0.y);
        x.y = bfp(m0.z + p0.z, m0.w + p0.w);
        x.z = bfp(m1.x + p1.x, m1.y + p1.y);
        x.w = bfp(m1.z + p1.z, m1.w + p1.w);
        *(uint4*)(sh + 8448 + srow * STRW + (cg >> 1)) = x;
    }
    sBias[tid] = bp[tid];
    if (tid < 128) sBest[tid] = 0ull;
    if (tid == 0) *sCnt = 0;
    __syncthreads();

    // ---- preload A fragments (A smem is dead after this) ------------------
    u32 af[64];
    {
        u32 abase = RingB + (wm * 16 + (lane & 15)) * 528 + ((lane >> 4) << 4);
#pragma unroll
        for (int ks = 0; ks < 16; ks++)
            LDSM4(af[ks * 4], af[ks * 4 + 1], af[ks * 4 + 2], af[ks * 4 + 3],
                  abase + ks * 32);
    }
    __syncthreads();

    // chunk sources: 0-7 = Wp quarters, 8-11 = Q quarters (for this n)
    const u32* qsrc = g_qB + n * 16384;
#define ISSUE_CHUNK(ch) do { \
        const u32* _s = ((ch) < 8) ? (g_WpB + (ch) * 4096) \
                                   : (qsrc + ((ch) - 8) * 4096); \
        u32 _d = RingB + ((ch) % 3) * 16896; \
        _Pragma("unroll") \
        for (int _it = 0; _it < 4; _it++) { \
            int _i = tid + _it * 256; \
            int _r = _i >> 5, _c4 = (_i & 31) * 4; \
            CPA16(_d + _r * 528 + _c4 * 4, _s + _r * 128 + _c4); \
        } \
        CPA_COMMIT(); \
    } while (0)

    ISSUE_CHUNK(0);
    ISSUE_CHUNK(1);

    float ss0 = 0.f, ss1 = 0.f;
    const int r0 = wm * 16 + gid;
    const u32 bgeo = (wj * 16 + (lane & 7) + ((lane >> 4) << 3)) * 528
                   + (((lane >> 3) & 1) << 4);

    // ---- phase 1: kp = A @ Wp^T, chunks 0..7 ------------------------------
#pragma unroll 1
    for (int c = 0; c < 8; c++) {
        CPA_WAIT1();
        __syncthreads();             // chunk c ready; buf[(c+2)%3] free
        ISSUE_CHUNK(c + 2);
        float ac0[4] = {0.f, 0.f, 0.f, 0.f};
        float ac1[4] = {0.f, 0.f, 0.f, 0.f};
        u32 bbase = RingB + (c % 3) * 16896 + bgeo;
#pragma unroll
        for (int ks = 0; ks < 16; ks++) {
            u32 b0, b1, b2, b3;
            LDSM4(b0, b1, b2, b3, bbase + ks * 32);
            MMA16816(ac0, af[ks*4], af[ks*4+1], af[ks*4+2], af[ks*4+3], b0, b1);
            MMA16816(ac1, af[ks*4], af[ks*4+1], af[ks*4+2], af[ks*4+3], b2, b3);
        }
        // epilogue: +bias, bf16 kp -> Kb, norm partials (private rows/words)
        {
            int jg = c * 32 + wj * 16 + tig * 2;
            float b0f = sBias[jg], b1f = sBias[jg + 1];
            float v0 = ac0[0] + b0f, v1 = ac0[1] + b1f;
            float v2 = ac0[2] + b0f, v3 = ac0[3] + b1f;
            Kb[r0 * STRW + (jg >> 1)] = bfp(v0, v1);
            Kb[(r0 + 8) * STRW + (jg >> 1)] = bfp(v2, v3);
            ss0 = fmaf(v0, v0, fmaf(v1, v1, ss0));
            ss1 = fmaf(v2, v2, fmaf(v3, v3, ss1));
            jg += 8;
            b0f = sBias[jg]; b1f = sBias[jg + 1];
            v0 = ac1[0] + b0f; v1 = ac1[1] + b1f;
            v2 = ac1[2] + b0f; v3 = ac1[3] + b1f;
            Kb[r0 * STRW + (jg >> 1)] = bfp(v0, v1);
            Kb[(r0 + 8) * STRW + (jg >> 1)] = bfp(v2, v3);
            ss0 = fmaf(v0, v0, fmaf(v1, v1, ss0));
            ss1 = fmaf(v2, v2, fmaf(v3, v3, ss1));
        }
    }

    // norm partials -> smem (read after next top sync)
    ss0 += __shfl_xor_sync(0xFFFFFFFFu, ss0, 1);
    ss0 += __shfl_xor_sync(0xFFFFFFFFu, ss0, 2);
    ss1 += __shfl_xor_sync(0xFFFFFFFFu, ss1, 1);
    ss1 += __shfl_xor_sync(0xFFFFFFFFu, ss1, 2);
    if (tig == 0) {
        sNorm[r0 * 2 + wj] = ss0;
        sNorm[(r0 + 8) * 2 + wj] = ss1;
    }

    // ---- phase 2: logits = Q @ kp^T, chunks 8..11 -------------------------
    const int sw = wm, lw = wj;                  // reuse role split
    const u32 ageo2 = (lw * 16 + (lane & 15)) * 528 + ((lane >> 4) << 4);
    const int sb = sw * 16;
    u32 bf[64];

#pragma unroll 1
    for (int c = 8; c < 12; c++) {
        if (c == 11) { CPA_WAIT0(); } else { CPA_WAIT1(); }
        __syncthreads();
        if (c <= 9) ISSUE_CHUNK(c + 2);
        if (c == 8) {
            if (tid < 64)
                sRsq[tid] = 1.0f / fmaxf(sqrtf(sNorm[tid * 2] + sNorm[tid * 2 + 1]),
                                         1e-12f);
            __syncthreads();
            // preload kp fragments from Kb (complete since chunk-7 epilogue)
            u32 kbase = KbB + (sw * 16 + (lane & 7) + ((lane >> 4) << 3)) * 528
                      + (((lane >> 3) & 1) << 4);
#pragma unroll
            for (int ks = 0; ks < 16; ks++)
                LDSM4(bf[ks * 4], bf[ks * 4 + 1], bf[ks * 4 + 2], bf[ks * 4 + 3],
                      kbase + ks * 32);
        }
        const int cc = c - 8;
        float ac0[4] = {0.f, 0.f, 0.f, 0.f};
        float ac1[4] = {0.f, 0.f, 0.f, 0.f};
        u32 abase = RingB + (c % 3) * 16896 + ageo2;
#pragma unroll
        for (int ks = 0; ks < 16; ks++) {
            u32 a0, a1, a2, a3;
            LDSM4(a0, a1, a2, a3, abase + ks * 32);
            MMA16816(ac0, a0, a1, a2, a3, bf[ks * 4], bf[ks * 4 + 1]);
            MMA16816(ac1, a0, a1, a2, a3, bf[ks * 4 + 2], bf[ks * 4 + 3]);
        }
        // epilogue2: scale, per-l tile max via sBest, emit candidates
        float ra = sRsq[sb + tig * 2],     rb2 = sRsq[sb + tig * 2 + 1];
        float rc = sRsq[sb + 8 + tig * 2], rd = sRsq[sb + 8 + tig * 2 + 1];
        float v00 = ac0[0] * ra, v01 = ac0[1] * rb2;
        float v02 = ac1[0] * rc, v03 = ac1[1] * rd;     // l0 values
        float v10 = ac0[2] * ra, v11 = ac0[3] * rb2;
        float v12 = ac1[2] * rc, v13 = ac1[3] * rd;     // l1 values
        int s00 = srow0 + sb + tig * 2;
        int l0 = cc * 32 + lw * 16 + gid, l1 = l0 + 8;

        float bv0 = v00; int bs0 = s00;
        if (v01 > bv0) { bv0 = v01; bs0 = s00 + 1; }
        if (v02 > bv0) { bv0 = v02; bs0 = s00 + 8; }
        if (v03 > bv0) { bv0 = v03; bs0 = s00 + 9; }
        float bv1 = v10; int bs1 = s00;
        if (v11 > bv1) { bv1 = v11; bs1 = s00 + 1; }
        if (v12 > bv1) { bv1 = v12; bs1 = s00 + 8; }
        if (v13 > bv1) { bv1 = v13; bs1 = s00 + 9; }
        ull p0 = ((ull)fkey(bv0) << 32) | (ull)(0xFFFFFFFFu - (u32)bs0);
        ull p1 = ((ull)fkey(bv1) << 32) | (ull)(0xFFFFFFFFu - (u32)bs1);
#pragma unroll
        for (int m = 1; m <= 2; m <<= 1) {
            ull o = __shfl_xor_sync(0xFFFFFFFFu, p0, m); if (o > p0) p0 = o;
            o = __shfl_xor_sync(0xFFFFFFFFu, p1, m); if (o > p1) p1 = o;
        }
        if (tig == 0) {
            atomicMax(&sBest[l0], p0);
            atomicMax(&sBest[l1], p1);
        }
        __syncthreads();
        // global atomicMax WITH return: threshold folds in stale global best
        if (tid < 32) {
            int lg = cc * 32 + tid;
            ull sbv = sBest[lg];
            ull old = atomicMax(&g_bestA[n * L_ + lg], sbv);
            sThr[tid] = fmaxf(unfkey((u32)(sbv >> 32)),
                              unfkey((u32)(old >> 32))) - MARGIN;
        }
        __syncthreads();
        {
            float t0 = sThr[lw * 16 + gid], t1 = sThr[lw * 16 + gid + 8];
#define EMIT(v, s, l, thr) \
            if ((v) >= (thr)) { \
                u32 key = ((u32)n << 21) | ((u32)(l) << 14) | (u32)(s); \
                int ci = atomicAdd(sCnt, 1); \
                if (ci < SCAND_CAP) { \
                    sCand[ci] = make_uint2(key, __float_as_uint(v)); \
                } else { \
                    int gi = atomicAdd(&g_ncand, 1); \
                    if (gi < CAND_CAP) \
                        g_cand[gi] = make_uint2(key, __float_as_uint(v)); \
                } \
            }
            EMIT(v00, s00,     l0, t0); EMIT(v01, s00 + 1, l0, t0);
            EMIT(v02, s00 + 8, l0, t0); EMIT(v03, s00 + 9, l0, t0);
            EMIT(v10, s00,     l1, t1); EMIT(v11, s00 + 1, l1, t1);
            EMIT(v12, s00 + 8, l1, t1); EMIT(v13, s00 + 9, l1, t1);
#undef EMIT
        }
    }

    // ---- flush candidate buffer: one global atomic per CTA ----------------
    __syncthreads();
    int cnt = *sCnt;
    if (cnt > SCAND_CAP) cnt = SCAND_CAP;
    if (tid == 0) *sBase = atomicAdd(&g_ncand, cnt);
    __syncthreads();
    {
        int base = *sBase;
        for (int i = tid; i < cnt; i += 256) {
            int gi = base + i;
            if (gi < CAND_CAP) g_cand[gi] = sCand[i];
        }
    }
#undef ISSUE_CHUNK
}

// ---------------- merged filter + refine (MLP-16 exact GEMV) ----------------
__global__ void __launch_bounds__(256)
refineKernel(const float* __restrict__ memory, const float* __restrict__ pos,
             const float* __restrict__ bp) {
    __shared__ float aS[8 * 260];
    __shared__ float qS[8 * 260];
    __shared__ float red[2][8][8];
    __shared__ uint2 eS[8];
    __shared__ uint2 list[2048];
    __shared__ int lcnt;
    const int tid = threadIdx.x;

    int nc = g_ncand; if (nc > CAND_CAP) nc = CAND_CAP;
    int per = (nc + 127) >> 7;
    int bstart = blockIdx.x * per;
    int bend = bstart + per; if (bend > nc) bend = nc;

    for (int pbase = bstart; pbase < bend; pbase += 2048) {
        int pend = pbase + 2048; if (pend > bend) pend = bend;
        if (tid == 0) lcnt = 0;
        __syncthreads();
        // filter this slice against converged approx global max
        for (int i = pbase + tid; i < pend; i += 256) {
            uint2 e = g_cand[i];
            int nn = (e.x >> 21) & 7, ll = (e.x >> 14) & 127;
            float gmax = unfkey((u32)(g_bestA[nn * L_ + ll] >> 32));
            if (__uint_as_float(e.y) >= gmax - MARGIN)
                list[atomicAdd(&lcnt, 1)] = e;   // bounded by slice size 2048
        }
        __syncthreads();
        int cnt = lcnt;
        // refine survivors exactly (fp32), 8 at a time
        for (int g = 0; g < cnt; g += 8) {
            if (tid < 8)
                eS[tid] = (g + tid < cnt) ? list[g + tid]
                                          : make_uint2(0xFFFFFFFFu, 0);
            __syncthreads();
#pragma unroll
            for (int r = 0; r < 8; r++) {
                uint2 e = eS[r];
                bool valid = (e.x != 0xFFFFFFFFu);
                int nn = valid ? (int)((e.x >> 21) & 7) : 0;
                int ll = valid ? (int)((e.x >> 14) & 127) : 0;
                int s  = valid ? (int)(e.x & 0x3FFF) : 0;
                int ga = (s * N_ + nn) * C_ + tid;
                aS[r * 260 + tid] = memory[ga] + pos[ga];
                qS[r * 260 + tid] = g_qproj[(nn * L_ + ll) * C_ + tid];
            }
            __syncthreads();

            const int j = tid;
            float kp[8];
#pragma unroll
            for (int r = 0; r < 8; r++) kp[r] = bp[j];
#pragma unroll 1
            for (int c0 = 0; c0 < C_; c0 += 16) {
                float wv[16];
#pragma unroll
                for (int i = 0; i < 16; i++)
                    wv[i] = g_WpT[(c0 + i) * C_ + j];
#pragma unroll
                for (int i = 0; i < 16; i++) {
#pragma unroll
                    for (int r = 0; r < 8; r++)
                        kp[r] = fmaf(aS[r * 260 + c0 + i], wv[i], kp[r]);
                }
            }
            const int lane = tid & 31, wrp = tid >> 5;
#pragma unroll
            for (int r = 0; r < 8; r++) {
                float v2 = kp[r] * kp[r];
                float vq = kp[r] * qS[r * 260 + j];
#pragma unroll
                for (int m = 16; m >= 1; m >>= 1) {
                    v2 += __shfl_xor_sync(0xFFFFFFFFu, v2, m);
                    vq += __shfl_xor_sync(0xFFFFFFFFu, vq, m);
                }
                if (lane == 0) { red[0][r][wrp] = v2; red[1][r][wrp] = vq; }
            }
            __syncthreads();
            if (tid < 8) {
                const int r = tid;
                float ss = 0.f, qq = 0.f;
#pragma unroll
                for (int ww = 0; ww < 8; ww++) {
                    ss += red[0][r][ww]; qq += red[1][r][ww];
                }
                uint2 e = eS[r];
                if (e.x != 0xFFFFFFFFu) {
                    int nn = (e.x >> 21) & 7, ll = (e.x >> 14) & 127;
                    u32 s = e.x & 0x3FFF;
                    float rsq = 1.0f / fmaxf(sqrtf(ss), 1e-12f);
                    float logit = qq * rsq;
                    atomicMax(&g_bestE[nn * L_ + ll],
                              ((ull)fkey(logit) << 32) | (ull)(0xFFFFFFFFu - s));
                }
            }
            __syncthreads();
        }
        __syncthreads();
    }
}

// ---------------- epilogue: winners -> v -> upd -> residual + LN ------------
__device__ __forceinline__ void gemvT(const float* inb, float* outb,
                                      const float* __restrict__ WT,
                                      const float* __restrict__ bias, int j) {
    float acc[8];
#pragma unroll
    for (int r = 0; r < 8; r++) acc[r] = bias[j];
#pragma unroll 4
    for (int c = 0; c < C_; c++) {
        float wv = WT[c * C_ + j];
#pragma unroll
        for (int r = 0; r < 8; r++) acc[r] = fmaf(inb[r * 260 + c], wv, acc[r]);
    }
#pragma unroll
    for (int r = 0; r < 8; r++) outb[r * 260 + j] = acc[r];
}

__global__ void __launch_bounds__(256)
finalKernel(const float* __restrict__ tgt, const float* __restrict__ memory,
            const float* __restrict__ pos,
            const float* __restrict__ bp, const float* __restrict__ bv,
            const float* __restrict__ bo,
            const float* __restrict__ gamma, const float* __restrict__ beta,
            float* __restrict__ out) {
    __shared__ float bufX[8 * 260];
    __shared__ float bufY[8 * 260];
    __shared__ unsigned sidx[8];
    const int tid = threadIdx.x;
    const int b = blockIdx.x;
    const int n = b >> 4;

    if (tid < 8) {
        ull pk = g_bestE[b * 8 + tid];
        sidx[tid] = 0xFFFFFFFFu - (unsigned)(pk & 0xFFFFFFFFu);
    }
    __syncthreads();

    for (int idx = tid; idx < 8 * 256; idx += 256) {
        int r = idx >> 8, j = idx & 255;
        int s = (int)sidx[r];
        int g = (s * N_ + n) * C_ + j;
        bufX[r * 260 + j] = memory[g] + pos[g];
    }
    __syncthreads();
    gemvT(bufX, bufY, g_WpT, bp, tid);  __syncthreads();
    gemvT(bufY, bufX, g_WvT, bv, tid);  __syncthreads();
    gemvT(bufX, bufY, g_WoT, bo, tid);  __syncthreads();

#pragma unroll
    for (int r = 0; r < 8; r++) {
        int l = (b & 15) * 8 + r;
        bufY[r * 260 + tid] += tgt[(l * N_ + n) * C_ + tid];
    }
    __syncthreads();

    const int w = tid >> 5, lane = tid & 31;
    float s1 = 0.f, s2 = 0.f;
#pragma unroll
    for (int k = 0; k < 8; k++) {
        float v = bufY[w * 260 + lane + k * 32];
        s1 += v;
        s2 = fmaf(v, v, s2);
    }
#pragma unroll
    for (int m = 16; m >= 1; m >>= 1) {
        s1 += __shfl_xor_sync(0xFFFFFFFFu, s1, m);
        s2 += __shfl_xor_sync(0xFFFFFFFFu, s2, m);
    }
    float mu = s1 * (1.0f / 256.0f);
    float var = s2 * (1.0f / 256.0f) - mu * mu;
    float rstd = rsqrtf(var + 1e-5f);

    int l = (b & 15) * 8 + w;
    float* o = out + (l * N_ + n) * C_;
#pragma unroll
    for (int k = 0; k < 8; k++) {
        int j = lane + k * 32;
        float v = bufY[w * 260 + j];
        o[j] = (v - mu) * rstd * gamma[j] + beta[j];
    }
}

// ============================================================================
extern "C" void kernel_launch(void* const* d_in, const int* in_sizes, int n_in,
                              void* d_out, int out_size) {
    const float* tgt    = (const float*)d_in[0];
    const float* memory = (const float*)d_in[1];
    const float* pos    = (const float*)d_in[2];
    const float* qpos   = (const float*)d_in[3];
    const float* Wq     = (const float*)d_in[4];
    const float* bq     = (const float*)d_in[5];
    const float* Wp     = (const float*)d_in[6];
    const float* bp     = (const float*)d_in[7];
    const float* Wv     = (const float*)d_in[8];
    const float* bv     = (const float*)d_in[9];
    const float* Wo     = (const float*)d_in[10];
    const float* bo     = (const float*)d_in[11];
    const float* gamma  = (const float*)d_in[12];
    const float* beta   = (const float*)d_in[13];
    float* out = (float*)d_out;

    cudaFuncSetAttribute(fusedMMA, cudaFuncAttributeMaxDynamicSharedMemorySize,
                         SMEM_BYTES);

    convWKernel<<<256, 256>>>(Wp, Wv, Wo);                              // 1
    qprojKernel<<<64, 256>>>(tgt, qpos, Wq, bq);                        // 2
    fusedMMA<<<dim3(S_ / 64, N_), 256, SMEM_BYTES>>>(memory, pos, bp);  // 3
    refineKernel<<<128, 256>>>(memory, pos, bp);                        // 4 -> profiled
    finalKernel<<<128, 256>>>(tgt, memory, pos, bp, bv, bo,
                              gamma, beta, out);                        // 5
}

// round 13
// speedup vs baseline: 1.3388x; 1.3388x over previous
#include <cuda_runtime.h>
#include <cstdint>
#include <math.h>

#define L_ 128
#define N_ 8
#define S_ 16384
#define C_ 256
#define MARGIN 0.08f
#define CAND_CAP (1 << 20)
#define SCAND_CAP 640
#define RBLK 512

typedef unsigned long long ull;
typedef unsigned int u32;

// ---------------- device scratch (no allocations allowed) -------------------
__device__ float g_qproj[N_ * L_ * C_];          // exact fp32 q_proj [n][l][c]
__device__ u32   g_qB[N_ * L_ * C_ / 2];         // bf16x2 Q, [n][l][c/2]
__device__ u32   g_WpB[C_ * C_ / 2];             // bf16x2 Wp, [j][c/2] linear
__device__ float g_WpT[C_ * C_];                 // fp32 transposed weights [c][j]
__device__ float g_WvT[C_ * C_];
__device__ float g_WoT[C_ * C_];
__device__ ull   g_bestA[N_ * L_];               // approx packed max
__device__ ull   g_bestE[N_ * L_];               // exact packed max
__device__ int   g_ncand;
__device__ uint2 g_cand[CAND_CAP];               // {key = n<<21|l<<14|s, approx_bits}

// ---------------- small helpers --------------------------------------------
__device__ __forceinline__ ull pk2(float a, float b) {
    ull r; asm("mov.b64 %0, {%1, %2};" : "=l"(r) : "f"(a), "f"(b)); return r;
}
__device__ __forceinline__ void up2(ull v, float &a, float &b) {
    asm("mov.b64 {%0, %1}, %2;" : "=f"(a), "=f"(b) : "l"(v));
}
#define FMA2(d, a, b) asm("fma.rn.f32x2 %0, %1, %2, %0;" : "+l"(d) : "l"(a), "l"(b))

__device__ __forceinline__ u32 fkey(float f) {
    u32 u = __float_as_uint(f);
    return (u & 0x80000000u) ? ~u : (u | 0x80000000u);
}
__device__ __forceinline__ float unfkey(u32 k) {
    return (k & 0x80000000u) ? __uint_as_float(k & 0x7FFFFFFFu)
                             : __uint_as_float(~k);
}
__device__ __forceinline__ u32 bfp(float lo, float hi) {   // bf16x2 {hi|lo}
    u32 r; asm("cvt.rn.bf16x2.f32 %0, %1, %2;" : "=r"(r) : "f"(hi), "f"(lo));
    return r;
}
__device__ __forceinline__ u32 smem_u32(const void* p) {
    u32 a;
    asm("{ .reg .u64 t; cvta.to.shared.u64 t, %1; cvt.u32.u64 %0, t; }"
        : "=r"(a) : "l"(p));
    return a;
}

// mma.sync m16n8k16 row.col bf16 -> f32 accum
#define MMA16816(c, a0, a1, a2, a3, b0, b1) \
    asm volatile("mma.sync.aligned.m16n8k16.row.col.f32.bf16.bf16.f32 " \
        "{%0,%1,%2,%3}, {%4,%5,%6,%7}, {%8,%9}, {%0,%1,%2,%3};" \
        : "+f"((c)[0]), "+f"((c)[1]), "+f"((c)[2]), "+f"((c)[3]) \
        : "r"(a0), "r"(a1), "r"(a2), "r"(a3), "r"(b0), "r"(b1))

#define LDSM4(d0, d1, d2, d3, a) \
    asm volatile("ldmatrix.sync.aligned.m8n8.x4.shared.b16 {%0,%1,%2,%3}, [%4];" \
        : "=r"(d0), "=r"(d1), "=r"(d2), "=r"(d3) : "r"(a))

#define CPA16(dst, src) \
    asm volatile("cp.async.cg.shared.global [%0], [%1], 16;" \
        :: "r"(dst), "l"(src))
#define CPA_COMMIT() asm volatile("cp.async.commit_group;")
#define CPA_WAIT1()  asm volatile("cp.async.wait_group 1;")
#define CPA_WAIT0()  asm volatile("cp.async.wait_group 0;")

// ---------------- weight prep: transposes + bf16 Wp + init ------------------
__global__ void __launch_bounds__(256)
convWKernel(const float* __restrict__ Wp, const float* __restrict__ Wv,
            const float* __restrict__ Wo) {
    int j = blockIdx.x;
    int c = threadIdx.x;
    if (j < 4) {
        int i = j * 256 + c;
        ull iv = ((ull)fkey(-1e30f)) << 32;
        g_bestA[i] = iv;
        g_bestE[i] = iv;
        if (i == 0) g_ncand = 0;
    }
    float wp = Wp[j * C_ + c];
    g_WpT[c * C_ + j] = wp;
    g_WvT[c * C_ + j] = Wv[j * C_ + c];
    g_WoT[c * C_ + j] = Wo[j * C_ + c];
    if ((c & 1) == 0) {
        float wp1 = Wp[j * C_ + c + 1];
        g_WpB[j * 128 + (c >> 1)] = bfp(wp, wp1);
    }
}

// ---------------- exact fp32 q_proj (FFMA2), 64 blocks x 16 rows ------------
__global__ void __launch_bounds__(256)
qprojKernel(const float* __restrict__ tgt, const float* __restrict__ qpos,
            const float* __restrict__ Wq, const float* __restrict__ bq) {
    __shared__ float As[16 * 33];
    __shared__ float Bs[32 * 258];
    const int tid = threadIdx.x;
    const int tj = tid & 15;
    const int ts = tid >> 4;
    const int row0 = blockIdx.x * 16;

    ull acc[8];
#pragma unroll
    for (int k = 0; k < 8; k++) {
        int j = 32 * k + tj * 2;
        acc[k] = pk2(bq[j], bq[j + 1]);
    }

    for (int kc = 0; kc < C_; kc += 32) {
        if (tid < 128) {
            int lr = tid >> 3, c4 = (tid & 7) * 4;
            int g = (row0 + lr) * C_ + kc + c4;
            float4 a = *(const float4*)(tgt + g);
            float4 b = *(const float4*)(qpos + g);
            float* d = As + lr * 33 + c4;
            d[0] = a.x + b.x; d[1] = a.y + b.y; d[2] = a.z + b.z; d[3] = a.w + b.w;
        }
        {
            int lr = tid >> 1, lh = tid & 1;
#pragma unroll
            for (int it = 0; it < 2; it++) {
                int j = lr + it * 128;
                const float4* pw = (const float4*)(Wq + j * C_ + kc + lh * 16);
#pragma unroll
                for (int i = 0; i < 4; i++) {
                    float4 w = pw[i];
                    int c = lh * 16 + i * 4;
                    Bs[(c + 0) * 258 + j] = w.x;
                    Bs[(c + 1) * 258 + j] = w.y;
                    Bs[(c + 2) * 258 + j] = w.z;
                    Bs[(c + 3) * 258 + j] = w.w;
                }
            }
        }
        __syncthreads();
#pragma unroll 4
        for (int c = 0; c < 32; c++) {
            float av = As[ts * 33 + c];
            ull a2 = pk2(av, av);
#pragma unroll
            for (int k = 0; k < 8; k++) {
                ull b2 = *(const ull*)(Bs + c * 258 + 32 * k + tj * 2);
                FMA2(acc[k], a2, b2);
            }
        }
        __syncthreads();
    }

    int row = row0 + ts;
    int l = row >> 3, n = row & 7;
    float* of = g_qproj + (n * L_ + l) * C_;
#pragma unroll
    for (int k = 0; k < 8; k++) {
        int j = 32 * k + tj * 2;
        *(ull*)(of + j) = acc[k];
        float f0, f1; up2(acc[k], f0, f1);
        g_qB[n * 16384 + l * 128 + (j >> 1)] = bfp(f0, f1);
    }
}

// ---------------- fused mma.sync kernel: unified 12-chunk ring --------------
// Tile: 64 s-rows per block; grid (256, 8). occ 2 (reg bound).
#define STRW 132
#define SMEM_WORDS 23140
#define SMEM_BYTES (SMEM_WORDS * 4)     // 92560

__global__ void __launch_bounds__(256, 2)
fusedMMA(const float* __restrict__ memory, const float* __restrict__ pos,
         const float* __restrict__ bp) {
    extern __shared__ u32 sh[];
    u32* Kb = sh;                              // words 0..8447
    float* sNorm = (float*)(sh + 21120);
    float* sRsq  = (float*)(sh + 21248);
    float* sBias = (float*)(sh + 21312);
    ull*   sBest = (ull*)(sh + 21568);
    int*   sCnt  = (int*)(sh + 21824);
    int*   sBase = (int*)(sh + 21825);
    uint2* sCand = (uint2*)(sh + 21826);       // 640 x uint2 -> ends 23106
    float* sThr  = (float*)(sh + 23106);       // 32 floats

    const int tid = threadIdx.x, lane = tid & 31, w = tid >> 5;
    const int gid = lane >> 2, tig = lane & 3;
    const int wm = w >> 1, wj = w & 1;         // role split (rows x half)
    const int n = blockIdx.y;
    const int srow0 = blockIdx.x * 64;

    const u32 shB = smem_u32(sh);
    const u32 KbB = shB;
    const u32 RingB = shB + 33792;             // 3 x 16896-byte buffers

    // ---- prologue: stage A = bf16(memory+pos) into ring bufs 0-1 ----------
#pragma unroll
    for (int it = 0; it < 8; it++) {
        int idx = tid + it * 256;
        int srow = idx >> 5, cg = (idx & 31) * 8;
        int ga = ((srow0 + srow) * N_ + n) * C_ + cg;
        float4 m0 = *(const float4*)(memory + ga);
        float4 m1 = *(const float4*)(memory + ga + 4);
        float4 p0 = *(const float4*)(pos + ga);
        float4 p1 = *(const float4*)(pos + ga + 4);
        uint4 x;
        x.x = bfp(m0.x + p0.x, m0.y + p0.y);
        x.y = bfp(m0.z + p0.z, m0.w + p0.w);
        x.z = bfp(m1.x + p1.x, m1.y + p1.y);
        x.w = bfp(m1.z + p1.z, m1.w + p1.w);
        *(uint4*)(sh + 8448 + srow * STRW + (cg >> 1)) = x;
    }
    sBias[tid] = bp[tid];
    if (tid < 128) sBest[tid] = 0ull;
    if (tid == 0) *sCnt = 0;
    __syncthreads();

    // ---- preload A fragments (A smem is dead after this) ------------------
    u32 af[64];
    {
        u32 abase = RingB + (wm * 16 + (lane & 15)) * 528 + ((lane >> 4) << 4);
#pragma unroll
        for (int ks = 0; ks < 16; ks++)
            LDSM4(af[ks * 4], af[ks * 4 + 1], af[ks * 4 + 2], af[ks * 4 + 3],
                  abase + ks * 32);
    }
    __syncthreads();

    // chunk sources: 0-7 = Wp quarters, 8-11 = Q quarters (for this n)
    const u32* qsrc = g_qB + n * 16384;
#define ISSUE_CHUNK(ch) do { \
        const u32* _s = ((ch) < 8) ? (g_WpB + (ch) * 4096) \
                                   : (qsrc + ((ch) - 8) * 4096); \
        u32 _d = RingB + ((ch) % 3) * 16896; \
        _Pragma("unroll") \
        for (int _it = 0; _it < 4; _it++) { \
            int _i = tid + _it * 256; \
            int _r = _i >> 5, _c4 = (_i & 31) * 4; \
            CPA16(_d + _r * 528 + _c4 * 4, _s + _r * 128 + _c4); \
        } \
        CPA_COMMIT(); \
    } while (0)

    ISSUE_CHUNK(0);
    ISSUE_CHUNK(1);

    float ss0 = 0.f, ss1 = 0.f;
    const int r0 = wm * 16 + gid;
    const u32 bgeo = (wj * 16 + (lane & 7) + ((lane >> 4) << 3)) * 528
                   + (((lane >> 3) & 1) << 4);

    // ---- phase 1: kp = A @ Wp^T, chunks 0..7 ------------------------------
#pragma unroll 1
    for (int c = 0; c < 8; c++) {
        CPA_WAIT1();
        __syncthreads();             // chunk c ready; buf[(c+2)%3] free
        ISSUE_CHUNK(c + 2);
        float ac0[4] = {0.f, 0.f, 0.f, 0.f};
        float ac1[4] = {0.f, 0.f, 0.f, 0.f};
        u32 bbase = RingB + (c % 3) * 16896 + bgeo;
#pragma unroll
        for (int ks = 0; ks < 16; ks++) {
            u32 b0, b1, b2, b3;
            LDSM4(b0, b1, b2, b3, bbase + ks * 32);
            MMA16816(ac0, af[ks*4], af[ks*4+1], af[ks*4+2], af[ks*4+3], b0, b1);
            MMA16816(ac1, af[ks*4], af[ks*4+1], af[ks*4+2], af[ks*4+3], b2, b3);
        }
        // epilogue: +bias, bf16 kp -> Kb, norm partials (private rows/words)
        {
            int jg = c * 32 + wj * 16 + tig * 2;
            float b0f = sBias[jg], b1f = sBias[jg + 1];
            float v0 = ac0[0] + b0f, v1 = ac0[1] + b1f;
            float v2 = ac0[2] + b0f, v3 = ac0[3] + b1f;
            Kb[r0 * STRW + (jg >> 1)] = bfp(v0, v1);
            Kb[(r0 + 8) * STRW + (jg >> 1)] = bfp(v2, v3);
            ss0 = fmaf(v0, v0, fmaf(v1, v1, ss0));
            ss1 = fmaf(v2, v2, fmaf(v3, v3, ss1));
            jg += 8;
            b0f = sBias[jg]; b1f = sBias[jg + 1];
            v0 = ac1[0] + b0f; v1 = ac1[1] + b1f;
            v2 = ac1[2] + b0f; v3 = ac1[3] + b1f;
            Kb[r0 * STRW + (jg >> 1)] = bfp(v0, v1);
            Kb[(r0 + 8) * STRW + (jg >> 1)] = bfp(v2, v3);
            ss0 = fmaf(v0, v0, fmaf(v1, v1, ss0));
            ss1 = fmaf(v2, v2, fmaf(v3, v3, ss1));
        }
    }

    // norm partials -> smem (read after next top sync)
    ss0 += __shfl_xor_sync(0xFFFFFFFFu, ss0, 1);
    ss0 += __shfl_xor_sync(0xFFFFFFFFu, ss0, 2);
    ss1 += __shfl_xor_sync(0xFFFFFFFFu, ss1, 1);
    ss1 += __shfl_xor_sync(0xFFFFFFFFu, ss1, 2);
    if (tig == 0) {
        sNorm[r0 * 2 + wj] = ss0;
        sNorm[(r0 + 8) * 2 + wj] = ss1;
    }

    // ---- phase 2: logits = Q @ kp^T, chunks 8..11 -------------------------
    const int sw = wm, lw = wj;                  // reuse role split
    const u32 ageo2 = (lw * 16 + (lane & 15)) * 528 + ((lane >> 4) << 4);
    const int sb = sw * 16;
    u32 bf[64];

#pragma unroll 1
    for (int c = 8; c < 12; c++) {
        if (c == 11) { CPA_WAIT0(); } else { CPA_WAIT1(); }
        __syncthreads();
        if (c <= 9) ISSUE_CHUNK(c + 2);
        if (c == 8) {
            if (tid < 64)
                sRsq[tid] = 1.0f / fmaxf(sqrtf(sNorm[tid * 2] + sNorm[tid * 2 + 1]),
                                         1e-12f);
            __syncthreads();
            // preload kp fragments from Kb (complete since chunk-7 epilogue)
            u32 kbase = KbB + (sw * 16 + (lane & 7) + ((lane >> 4) << 3)) * 528
                      + (((lane >> 3) & 1) << 4);
#pragma unroll
            for (int ks = 0; ks < 16; ks++)
                LDSM4(bf[ks * 4], bf[ks * 4 + 1], bf[ks * 4 + 2], bf[ks * 4 + 3],
                      kbase + ks * 32);
        }
        const int cc = c - 8;
        float ac0[4] = {0.f, 0.f, 0.f, 0.f};
        float ac1[4] = {0.f, 0.f, 0.f, 0.f};
        u32 abase = RingB + (c % 3) * 16896 + ageo2;
#pragma unroll
        for (int ks = 0; ks < 16; ks++) {
            u32 a0, a1, a2, a3;
            LDSM4(a0, a1, a2, a3, abase + ks * 32);
            MMA16816(ac0, a0, a1, a2, a3, bf[ks * 4], bf[ks * 4 + 1]);
            MMA16816(ac1, a0, a1, a2, a3, bf[ks * 4 + 2], bf[ks * 4 + 3]);
        }
        // epilogue2: scale, per-l tile max via sBest, emit candidates
        float ra = sRsq[sb + tig * 2],     rb2 = sRsq[sb + tig * 2 + 1];
        float rc = sRsq[sb + 8 + tig * 2], rd = sRsq[sb + 8 + tig * 2 + 1];
        float v00 = ac0[0] * ra, v01 = ac0[1] * rb2;
        float v02 = ac1[0] * rc, v03 = ac1[1] * rd;     // l0 values
        float v10 = ac0[2] * ra, v11 = ac0[3] * rb2;
        float v12 = ac1[2] * rc, v13 = ac1[3] * rd;     // l1 values
        int s00 = srow0 + sb + tig * 2;
        int l0 = cc * 32 + lw * 16 + gid, l1 = l0 + 8;

        float bv0 = v00; int bs0 = s00;
        if (v01 > bv0) { bv0 = v01; bs0 = s00 + 1; }
        if (v02 > bv0) { bv0 = v02; bs0 = s00 + 8; }
        if (v03 > bv0) { bv0 = v03; bs0 = s00 + 9; }
        float bv1 = v10; int bs1 = s00;
        if (v11 > bv1) { bv1 = v11; bs1 = s00 + 1; }
        if (v12 > bv1) { bv1 = v12; bs1 = s00 + 8; }
        if (v13 > bv1) { bv1 = v13; bs1 = s00 + 9; }
        ull p0 = ((ull)fkey(bv0) << 32) | (ull)(0xFFFFFFFFu - (u32)bs0);
        ull p1 = ((ull)fkey(bv1) << 32) | (ull)(0xFFFFFFFFu - (u32)bs1);
#pragma unroll
        for (int m = 1; m <= 2; m <<= 1) {
            ull o = __shfl_xor_sync(0xFFFFFFFFu, p0, m); if (o > p0) p0 = o;
            o = __shfl_xor_sync(0xFFFFFFFFu, p1, m); if (o > p1) p1 = o;
        }
        if (tig == 0) {
            atomicMax(&sBest[l0], p0);
            atomicMax(&sBest[l1], p1);
        }
        __syncthreads();
        // global atomicMax WITH return: threshold folds in stale global best
        if (tid < 32) {
            int lg = cc * 32 + tid;
            ull sbv = sBest[lg];
            ull old = atomicMax(&g_bestA[n * L_ + lg], sbv);
            sThr[tid] = fmaxf(unfkey((u32)(sbv >> 32)),
                              unfkey((u32)(old >> 32))) - MARGIN;
        }
        __syncthreads();
        {
            float t0 = sThr[lw * 16 + gid], t1 = sThr[lw * 16 + gid + 8];
#define EMIT(v, s, l, thr) \
            if ((v) >= (thr)) { \
                u32 key = ((u32)n << 21) | ((u32)(l) << 14) | (u32)(s); \
                int ci = atomicAdd(sCnt, 1); \
                if (ci < SCAND_CAP) { \
                    sCand[ci] = make_uint2(key, __float_as_uint(v)); \
                } else { \
                    int gi = atomicAdd(&g_ncand, 1); \
                    if (gi < CAND_CAP) \
                        g_cand[gi] = make_uint2(key, __float_as_uint(v)); \
                } \
            }
            EMIT(v00, s00,     l0, t0); EMIT(v01, s00 + 1, l0, t0);
            EMIT(v02, s00 + 8, l0, t0); EMIT(v03, s00 + 9, l0, t0);
            EMIT(v10, s00,     l1, t1); EMIT(v11, s00 + 1, l1, t1);
            EMIT(v12, s00 + 8, l1, t1); EMIT(v13, s00 + 9, l1, t1);
#undef EMIT
        }
    }

    // ---- flush candidate buffer: one global atomic per CTA ----------------
    __syncthreads();
    int cnt = *sCnt;
    if (cnt > SCAND_CAP) cnt = SCAND_CAP;
    if (tid == 0) *sBase = atomicAdd(&g_ncand, cnt);
    __syncthreads();
    {
        int base = *sBase;
        for (int i = tid; i < cnt; i += 256) {
            int gi = base + i;
            if (gi < CAND_CAP) g_cand[gi] = sCand[i];
        }
    }
#undef ISSUE_CHUNK
}

// ---------------- merged filter + refine: 512 blocks, strided ---------------
__global__ void __launch_bounds__(256)
refineKernel(const float* __restrict__ memory, const float* __restrict__ pos,
             const float* __restrict__ bp) {
    __shared__ float aS[8 * 260];
    __shared__ float qS[8 * 260];
    __shared__ float red[2][8][8];
    __shared__ uint2 eS[8];
    __shared__ uint2 list[96];
    __shared__ int lcnt;
    const int tid = threadIdx.x;
    const int b = blockIdx.x;

    int nc = g_ncand; if (nc > CAND_CAP) nc = CAND_CAP;
    // block b owns candidate indices b + RBLK*k, k = 0..nk-1
    int nk = (nc > b) ? ((nc - b + RBLK - 1) / RBLK) : 0;
    int nk_max = (nc + RBLK - 1) / RBLK;   // uniform round count across blocks

    for (int k0 = 0; k0 < nk_max; k0 += 64) {
        if (tid == 0) lcnt = 0;
        __syncthreads();
        // scan up to 64 strided candidates this round; filter vs converged max
        {
            int k = k0 + tid;
            if (tid < 64 && k < nk) {
                int i = b + k * RBLK;
                uint2 e = g_cand[i];
                int nn = (e.x >> 21) & 7, ll = (e.x >> 14) & 127;
                float gmax = unfkey((u32)(g_bestA[nn * L_ + ll] >> 32));
                if (__uint_as_float(e.y) >= gmax - MARGIN)
                    list[atomicAdd(&lcnt, 1)] = e;
            }
        }
        __syncthreads();
        int cnt = lcnt;
        // refine survivors exactly (fp32), 8 at a time
        for (int g = 0; g < cnt; g += 8) {
            if (tid < 8)
                eS[tid] = (g + tid < cnt) ? list[g + tid]
                                          : make_uint2(0xFFFFFFFFu, 0);
            __syncthreads();
#pragma unroll
            for (int r = 0; r < 8; r++) {
                uint2 e = eS[r];
                bool valid = (e.x != 0xFFFFFFFFu);
                int nn = valid ? (int)((e.x >> 21) & 7) : 0;
                int ll = valid ? (int)((e.x >> 14) & 127) : 0;
                int s  = valid ? (int)(e.x & 0x3FFF) : 0;
                int ga = (s * N_ + nn) * C_ + tid;
                aS[r * 260 + tid] = memory[ga] + pos[ga];
                qS[r * 260 + tid] = g_qproj[(nn * L_ + ll) * C_ + tid];
            }
            __syncthreads();

            const int j = tid;
            float kp[8];
#pragma unroll
            for (int r = 0; r < 8; r++) kp[r] = bp[j];
#pragma unroll 1
            for (int c0 = 0; c0 < C_; c0 += 16) {
                float wv[16];
#pragma unroll
                for (int i = 0; i < 16; i++)
                    wv[i] = g_WpT[(c0 + i) * C_ + j];
#pragma unroll
                for (int i = 0; i < 16; i++) {
#pragma unroll
                    for (int r = 0; r < 8; r++)
                        kp[r] = fmaf(aS[r * 260 + c0 + i], wv[i], kp[r]);
                }
            }
            const int lane = tid & 31, wrp = tid >> 5;
#pragma unroll
            for (int r = 0; r < 8; r++) {
                float v2 = kp[r] * kp[r];
                float vq = kp[r] * qS[r * 260 + j];
#pragma unroll
                for (int m = 16; m >= 1; m >>= 1) {
                    v2 += __shfl_xor_sync(0xFFFFFFFFu, v2, m);
                    vq += __shfl_xor_sync(0xFFFFFFFFu, vq, m);
                }
                if (lane == 0) { red[0][r][wrp] = v2; red[1][r][wrp] = vq; }
            }
            __syncthreads();
            if (tid < 8) {
                const int r = tid;
                float ss = 0.f, qq = 0.f;
#pragma unroll
                for (int ww = 0; ww < 8; ww++) {
                    ss += red[0][r][ww]; qq += red[1][r][ww];
                }
                uint2 e = eS[r];
                if (e.x != 0xFFFFFFFFu) {
                    int nn = (e.x >> 21) & 7, ll = (e.x >> 14) & 127;
                    u32 s = e.x & 0x3FFF;
                    float rsq = 1.0f / fmaxf(sqrtf(ss), 1e-12f);
                    float logit = qq * rsq;
                    atomicMax(&g_bestE[nn * L_ + ll],
                              ((ull)fkey(logit) << 32) | (ull)(0xFFFFFFFFu - s));
                }
            }
            __syncthreads();
        }
        __syncthreads();
    }
}

// ---------------- epilogue: winners -> v -> upd -> residual + LN ------------
__device__ __forceinline__ void gemvT(const float* inb, float* outb,
                                      const float* __restrict__ WT,
                                      const float* __restrict__ bias, int j) {
    float acc[8];
#pragma unroll
    for (int r = 0; r < 8; r++) acc[r] = bias[j];
#pragma unroll 4
    for (int c = 0; c < C_; c++) {
        float wv = WT[c * C_ + j];
#pragma unroll
        for (int r = 0; r < 8; r++) acc[r] = fmaf(inb[r * 260 + c], wv, acc[r]);
    }
#pragma unroll
    for (int r = 0; r < 8; r++) outb[r * 260 + j] = acc[r];
}

__global__ void __launch_bounds__(256)
finalKernel(const float* __restrict__ tgt, const float* __restrict__ memory,
            const float* __restrict__ pos,
            const float* __restrict__ bp, const float* __restrict__ bv,
            const float* __restrict__ bo,
            const float* __restrict__ gamma, const float* __restrict__ beta,
            float* __restrict__ out) {
    __shared__ float bufX[8 * 260];
    __shared__ float bufY[8 * 260];
    __shared__ unsigned sidx[8];
    const int tid = threadIdx.x;
    const int b = blockIdx.x;
    const int n = b >> 4;

    if (tid < 8) {
        ull pk = g_bestE[b * 8 + tid];
        sidx[tid] = 0xFFFFFFFFu - (unsigned)(pk & 0xFFFFFFFFu);
    }
    __syncthreads();

    for (int idx = tid; idx < 8 * 256; idx += 256) {
        int r = idx >> 8, j = idx & 255;
        int s = (int)sidx[r];
        int g = (s * N_ + n) * C_ + j;
        bufX[r * 260 + j] = memory[g] + pos[g];
    }
    __syncthreads();
    gemvT(bufX, bufY, g_WpT, bp, tid);  __syncthreads();
    gemvT(bufY, bufX, g_WvT, bv, tid);  __syncthreads();
    gemvT(bufX, bufY, g_WoT, bo, tid);  __syncthreads();

#pragma unroll
    for (int r = 0; r < 8; r++) {
        int l = (b & 15) * 8 + r;
        bufY[r * 260 + tid] += tgt[(l * N_ + n) * C_ + tid];
    }
    __syncthreads();

    const int w = tid >> 5, lane = tid & 31;
    float s1 = 0.f, s2 = 0.f;
#pragma unroll
    for (int k = 0; k < 8; k++) {
        float v = bufY[w * 260 + lane + k * 32];
        s1 += v;
        s2 = fmaf(v, v, s2);
    }
#pragma unroll
    for (int m = 16; m >= 1; m >>= 1) {
        s1 += __shfl_xor_sync(0xFFFFFFFFu, s1, m);
        s2 += __shfl_xor_sync(0xFFFFFFFFu, s2, m);
    }
    float mu = s1 * (1.0f / 256.0f);
    float var = s2 * (1.0f / 256.0f) - mu * mu;
    float rstd = rsqrtf(var + 1e-5f);

    int l = (b & 15) * 8 + w;
    float* o = out + (l * N_ + n) * C_;
#pragma unroll
    for (int k = 0; k < 8; k++) {
        int j = lane + k * 32;
        float v = bufY[w * 260 + j];
        o[j] = (v - mu) * rstd * gamma[j] + beta[j];
    }
}

// ============================================================================
extern "C" void kernel_launch(void* const* d_in, const int* in_sizes, int n_in,
                              void* d_out, int out_size) {
    const float* tgt    = (const float*)d_in[0];
    const float* memory = (const float*)d_in[1];
    const float* pos    = (const float*)d_in[2];
    const float* qpos   = (const float*)d_in[3];
    const float* Wq     = (const float*)d_in[4];
    const float* bq     = (const float*)d_in[5];
    const float* Wp     = (const float*)d_in[6];
    const float* bp     = (const float*)d_in[7];
    const float* Wv     = (const float*)d_in[8];
    const float* bv     = (const float*)d_in[9];
    const float* Wo     = (const float*)d_in[10];
    const float* bo     = (const float*)d_in[11];
    const float* gamma  = (const float*)d_in[12];
    const float* beta   = (const float*)d_in[13];
    float* out = (float*)d_out;

    cudaFuncSetAttribute(fusedMMA, cudaFuncAttributeMaxDynamicSharedMemorySize,
                         SMEM_BYTES);

    convWKernel<<<256, 256>>>(Wp, Wv, Wo);                              // 1
    qprojKernel<<<64, 256>>>(tgt, qpos, Wq, bq);                        // 2
    fusedMMA<<<dim3(S_ / 64, N_), 256, SMEM_BYTES>>>(memory, pos, bp);  // 3
    refineKernel<<<RBLK, 256>>>(memory, pos, bp);                       // 4 -> profiled
    finalKernel<<<128, 256>>>(tgt, memory, pos, bp, bv, bo,
                              gamma, beta, out);                        // 5
}